// round 1
// baseline (speedup 1.0000x reference)
#include <cuda_runtime.h>
#include <math.h>

#define BSZ   16384
#define LSP   32
#define C1    128
#define C2    64
#define CH2   16        // batch rows per block in conv1-stats kernel

// ---- persistent device scratch (no allocations allowed) ----
__device__ float  g_images[BSZ * LSP];          //  2 MB
__device__ float  g_h2[BSZ * C2 * LSP];         //  134 MB (relu(conv2) activations)
__device__ double g_stats1[2 * C1];
__device__ double g_stats2[2 * C2];
__device__ float  g_a1[C1], g_c1[C1];
__device__ float  g_a2[C2], g_c2[C2];

// ------------------------------------------------------------------
__global__ void k_zero_stats() {
    int t = threadIdx.x;
    if (t < 2 * C1) g_stats1[t] = 0.0;
    if (t < 2 * C2) g_stats2[t] = 0.0;
}

// ------------------------------------------------------------------
// Quantum patches. Key simplification: given = probs[:8]/max(probs[:8])
// (the sum(probs) normalization cancels exactly in given0/max(given0)).
__global__ void k_images(const float* __restrict__ x, const float* __restrict__ qp) {
    int t = blockIdx.x * blockDim.x + threadIdx.x;
    if (t >= BSZ * 4) return;
    int b = t >> 2, g = t & 3;
    float c[4], s[4];
#pragma unroll
    for (int q = 0; q < 4; q++) {
        float th = 0.5f * (x[b * 4 + q] + qp[g * 4 + q]);
        c[q] = cosf(th);
        s[q] = sinf(th);
    }
    float p[8];
    float mx = 0.f;
#pragma unroll
    for (int i = 0; i < 8; i++) {
        float a = c[0];                       // kept states have qubit-0 bit == 0
        a *= ((i >> 2) & 1) ? s[1] : c[1];
        a *= ((i >> 1) & 1) ? s[2] : c[2];
        a *= (i & 1)        ? s[3] : c[3];
        float pp = a * a;                     // sign² == 1
        p[i] = pp;
        mx = fmaxf(mx, pp);
    }
    float inv = 1.0f / mx;
#pragma unroll
    for (int i = 0; i < 8; i++) g_images[b * 32 + g * 8 + i] = p[i] * inv;
}

// ------------------------------------------------------------------
// conv1 + relu, accumulate per-channel sum / sumsq. One thread per channel.
// y[oc,p] = b1[oc] + img[p-1]*w1[oc][2] + img[p]*w1[oc][1] + img[p+1]*w1[oc][0]
__global__ void k_conv1_stats(const float* __restrict__ w1, const float* __restrict__ b1) {
    __shared__ float sh[CH2][34];
    int tid = threadIdx.x;            // 128
    int b0 = blockIdx.x * CH2;
    for (int i = tid; i < CH2 * 32; i += 128)
        sh[i >> 5][(i & 31) + 1] = g_images[(b0 + (i >> 5)) * 32 + (i & 31)];
    if (tid < CH2) { sh[tid][0] = 0.f; sh[tid][33] = 0.f; }
    __syncthreads();

    int oc = tid;
    float wA = w1[oc * 3 + 2], wB = w1[oc * 3 + 1], wC = w1[oc * 3 + 0], bb = b1[oc];
    float sum = 0.f, sq = 0.f;
    for (int r = 0; r < CH2; r++) {
#pragma unroll
        for (int p = 0; p < 32; p++) {
            float y = bb + sh[r][p] * wA + sh[r][p + 1] * wB + sh[r][p + 2] * wC;
            y = fmaxf(y, 0.f);
            sum += y;
            sq += y * y;
        }
    }
    atomicAdd(&g_stats1[oc], (double)sum);
    atomicAdd(&g_stats1[C1 + oc], (double)sq);
}

// ------------------------------------------------------------------
__global__ void k_fin1(const float* __restrict__ gamma, const float* __restrict__ beta) {
    int c = threadIdx.x;
    if (c >= C1) return;
    double N = (double)BSZ * LSP;
    double mean = g_stats1[c] / N;
    double var = g_stats1[C1 + c] / N - mean * mean;
    float a = gamma[c] * (float)(1.0 / sqrt(var + 1e-5));
    g_a1[c] = a;
    g_c1[c] = beta[c] - (float)mean * a;
}

__global__ void k_fin2(const float* __restrict__ gamma, const float* __restrict__ beta) {
    int c = threadIdx.x;
    if (c >= C2) return;
    double N = (double)BSZ * LSP;
    double mean = g_stats2[c] / N;
    double var = g_stats2[C2 + c] / N - mean * mean;
    float a = gamma[c] * (float)(1.0 / sqrt(var + 1e-5));
    g_a2[c] = a;
    g_c2[c] = beta[c] - (float)mean * a;
}

// ------------------------------------------------------------------
// Fused: recompute conv1 -> relu -> BN1 affine -> h1n (smem, zero halos)
//        -> conv2 -> +bias -> relu -> store h2 -> per-channel stats2.
// Block = 256 threads, 4 batch rows. Dynamic smem partitions:
//   shn  : 4*128*34 floats (h1n with halo)
//   sw   : 32*192 floats   (w2 chunk, layout [icl][k*64+oc])
//   simg : 4*34
//   sp   : 128*6  (w1[0..2], b1, a1, c1 per channel)
//   red  : 128    (block-level channel reduction)
#define SMEM_FLOATS (4*128*34 + 32*192 + 4*34 + 128*6 + 128)

__global__ void __launch_bounds__(256, 2)
k_conv2(const float* __restrict__ w1, const float* __restrict__ b1,
        const float* __restrict__ w2, const float* __restrict__ b2) {
    extern __shared__ float sm[];
    float* shn  = sm;
    float* sw   = shn + 4 * 128 * 34;
    float* simg = sw + 32 * 192;
    float* sp   = simg + 4 * 34;
    float* red  = sp + 128 * 6;

    int tid = threadIdx.x;
    int bbase = blockIdx.x * 4;

    if (tid < 128) red[tid] = 0.f;
    for (int i = tid; i < 128; i += 256) {
        sp[i * 6 + 0] = w1[i * 3 + 0];
        sp[i * 6 + 1] = w1[i * 3 + 1];
        sp[i * 6 + 2] = w1[i * 3 + 2];
        sp[i * 6 + 3] = b1[i];
        sp[i * 6 + 4] = g_a1[i];
        sp[i * 6 + 5] = g_c1[i];
    }
    for (int i = tid; i < 4 * 32; i += 256) {
        int bl = i >> 5, p = i & 31;
        simg[bl * 34 + p + 1] = g_images[(bbase + bl) * 32 + p];
    }
    if (tid < 4) { simg[tid * 34] = 0.f; simg[tid * 34 + 33] = 0.f; }
    for (int i = tid; i < 4 * 128; i += 256) {
        shn[i * 34 + 0]  = 0.f;
        shn[i * 34 + 33] = 0.f;
    }
    __syncthreads();

    // h1n = a1 * relu(conv1) + c1  (padding positions stay 0)
    for (int idx = tid; idx < 4 * 128 * 32; idx += 256) {
        int bl = idx >> 12, rem = idx & 4095, ic = rem >> 5, p = rem & 31;
        const float* pp = &sp[ic * 6];
        float y = pp[3] + simg[bl * 34 + p] * pp[2] + simg[bl * 34 + p + 1] * pp[1]
                        + simg[bl * 34 + p + 2] * pp[0];
        y = fmaxf(y, 0.f);
        shn[(bl * 128 + ic) * 34 + p + 1] = fmaf(pp[4], y, pp[5]);
    }

    // conv2: thread = (bl, 4 out-channels, 8 positions)
    int bl = tid >> 6;
    int u = tid & 63;
    int ocbase = (u >> 2) * 4;
    int p0 = (u & 3) * 8;

    float acc[4][8];
#pragma unroll
    for (int j = 0; j < 4; j++)
#pragma unroll
        for (int i = 0; i < 8; i++) acc[j][i] = 0.f;

    const float* myrow = &shn[bl * 128 * 34];
    for (int chunk = 0; chunk < 4; chunk++) {
        __syncthreads();
        for (int i = tid; i < 32 * 192; i += 256) {
            int icl = i / 192, r = i - icl * 192;
            int k = r >> 6, oc = r & 63;
            sw[i] = w2[((chunk * 32 + icl) * 64 + oc) * 3 + k];
        }
        __syncthreads();
#pragma unroll 2
        for (int icl = 0; icl < 32; icl++) {
            int ic = chunk * 32 + icl;
            const float* xr = myrow + ic * 34 + p0;
            float xv[10];
#pragma unroll
            for (int i = 0; i < 10; i++) xv[i] = xr[i];
            const float* wr = &sw[icl * 192];
#pragma unroll
            for (int j = 0; j < 4; j++) {
                float wk2 = wr[2 * 64 + ocbase + j];
                float wk1 = wr[1 * 64 + ocbase + j];
                float wk0 = wr[0 * 64 + ocbase + j];
#pragma unroll
                for (int i = 0; i < 8; i++)
                    acc[j][i] += xv[i] * wk2 + xv[i + 1] * wk1 + xv[i + 2] * wk0;
            }
        }
    }

    int b = bbase + bl;
#pragma unroll
    for (int j = 0; j < 4; j++) {
        int oc = ocbase + j;
        float bb = b2[oc];
        float s = 0.f, sq = 0.f;
#pragma unroll
        for (int i = 0; i < 8; i++) {
            float y = fmaxf(acc[j][i] + bb, 0.f);
            g_h2[(b * 64 + oc) * 32 + p0 + i] = y;
            s += y;
            sq += y * y;
        }
        atomicAdd(&red[oc], s);
        atomicAdd(&red[64 + oc], sq);
    }
    __syncthreads();
    if (tid < 128) atomicAdd(&g_stats2[tid], (double)red[tid]);
}

// ------------------------------------------------------------------
// BN2 affine (zero padding applied AFTER BN, so halo contributes 0) + conv3 + tanh.
__global__ void k_conv3(const float* __restrict__ w3, const float* __restrict__ b3,
                        float* __restrict__ out) {
    __shared__ float sa[64], sc[64], swv[192], sb3;
    int tid = threadIdx.x;
    if (tid < 64) { sa[tid] = g_a2[tid]; sc[tid] = g_c2[tid]; }
    if (tid < 192) swv[tid] = w3[tid];
    if (tid == 0) sb3 = b3[0];
    __syncthreads();

    int t = blockIdx.x * 256 + tid;
    int b = t >> 5, p = t & 31;
    const float* base = &g_h2[b * 64 * 32];
    float acc = sb3;
#pragma unroll 4
    for (int ic = 0; ic < 64; ic++) {
        const float* row = base + ic * 32;
        float a = sa[ic], cs = sc[ic];
        float x0 = fmaf(a, row[p], cs);
        float xm = (p > 0)  ? fmaf(a, row[p - 1], cs) : 0.f;
        float xp = (p < 31) ? fmaf(a, row[p + 1], cs) : 0.f;
        acc += xm * swv[ic * 3 + 2] + x0 * swv[ic * 3 + 1] + xp * swv[ic * 3 + 0];
    }
    out[t] = tanhf(acc);
}

// ------------------------------------------------------------------
extern "C" void kernel_launch(void* const* d_in, const int* in_sizes, int n_in,
                              void* d_out, int out_size) {
    const float* x   = (const float*)d_in[0];
    const float* qp  = (const float*)d_in[1];
    const float* w1  = (const float*)d_in[2];
    const float* b1  = (const float*)d_in[3];
    const float* g1  = (const float*)d_in[4];
    const float* be1 = (const float*)d_in[5];
    const float* w2  = (const float*)d_in[6];
    const float* b2  = (const float*)d_in[7];
    const float* g2  = (const float*)d_in[8];
    const float* be2 = (const float*)d_in[9];
    const float* w3  = (const float*)d_in[10];
    const float* b3  = (const float*)d_in[11];
    float* out = (float*)d_out;

    const int smem_bytes = SMEM_FLOATS * (int)sizeof(float);
    cudaFuncSetAttribute(k_conv2, cudaFuncAttributeMaxDynamicSharedMemorySize, smem_bytes);

    k_zero_stats<<<1, 256>>>();
    k_images<<<(BSZ * 4) / 256, 256>>>(x, qp);
    k_conv1_stats<<<BSZ / CH2, 128>>>(w1, b1);
    k_fin1<<<1, 128>>>(g1, be1);
    k_conv2<<<BSZ / 4, 256, smem_bytes>>>(w1, b1, w2, b2);
    k_fin2<<<1, 64>>>(g2, be2);
    k_conv3<<<(BSZ * 32) / 256, 256>>>(w3, b3, out);
}

// round 2
// speedup vs baseline: 1.0433x; 1.0433x over previous
#include <cuda_runtime.h>
#include <math.h>

#define BSZ   16384
#define LSP   32
#define C1    128
#define C2    64
#define CH2   16        // batch rows per block in conv1-stats kernel

// ---- persistent device scratch (no allocations allowed) ----
__device__ float  g_images[BSZ * LSP];          //  2 MB
__device__ float  g_h2[BSZ * C2 * LSP];         //  134 MB (relu(conv2) activations)
__device__ double g_stats1[2 * C1];
__device__ double g_stats2[2 * C2];
__device__ float  g_a1[C1], g_c1[C1];
__device__ float  g_a2[C2], g_c2[C2];

// ---- packed f32x2 helpers (Blackwell double-rate fp32) ----
__device__ __forceinline__ unsigned long long pack2(float lo, float hi) {
    unsigned long long r;
    asm("mov.b64 %0, {%1, %2};" : "=l"(r)
        : "r"(__float_as_uint(lo)), "r"(__float_as_uint(hi)));
    return r;
}
__device__ __forceinline__ unsigned long long dup2(float v) {
    unsigned long long r;
    unsigned int u = __float_as_uint(v);
    asm("mov.b64 %0, {%1, %1};" : "=l"(r) : "r"(u));
    return r;
}
__device__ __forceinline__ void fma2(unsigned long long& acc,
                                     unsigned long long a, unsigned long long b) {
    asm("fma.rn.f32x2 %0, %1, %2, %0;" : "+l"(acc) : "l"(a), "l"(b));
}
__device__ __forceinline__ void unpack2(unsigned long long v, float& lo, float& hi) {
    unsigned int a, b;
    asm("mov.b64 {%0, %1}, %2;" : "=r"(a), "=r"(b) : "l"(v));
    lo = __uint_as_float(a);
    hi = __uint_as_float(b);
}

// ------------------------------------------------------------------
__global__ void k_zero_stats() {
    int t = threadIdx.x;
    if (t < 2 * C1) g_stats1[t] = 0.0;
    if (t < 2 * C2) g_stats2[t] = 0.0;
}

// ------------------------------------------------------------------
// Quantum patches. given = probs[:8]/max(probs[:8]) (sum-normalization cancels).
__global__ void k_images(const float* __restrict__ x, const float* __restrict__ qp) {
    int t = blockIdx.x * blockDim.x + threadIdx.x;
    if (t >= BSZ * 4) return;
    int b = t >> 2, g = t & 3;
    float c[4], s[4];
#pragma unroll
    for (int q = 0; q < 4; q++) {
        float th = 0.5f * (x[b * 4 + q] + qp[g * 4 + q]);
        c[q] = cosf(th);
        s[q] = sinf(th);
    }
    float p[8];
    float mx = 0.f;
#pragma unroll
    for (int i = 0; i < 8; i++) {
        float a = c[0];
        a *= ((i >> 2) & 1) ? s[1] : c[1];
        a *= ((i >> 1) & 1) ? s[2] : c[2];
        a *= (i & 1)        ? s[3] : c[3];
        float pp = a * a;
        p[i] = pp;
        mx = fmaxf(mx, pp);
    }
    float inv = 1.0f / mx;
#pragma unroll
    for (int i = 0; i < 8; i++) g_images[b * 32 + g * 8 + i] = p[i] * inv;
}

// ------------------------------------------------------------------
__global__ void k_conv1_stats(const float* __restrict__ w1, const float* __restrict__ b1) {
    __shared__ float sh[CH2][34];
    int tid = threadIdx.x;            // 128
    int b0 = blockIdx.x * CH2;
    for (int i = tid; i < CH2 * 32; i += 128)
        sh[i >> 5][(i & 31) + 1] = g_images[(b0 + (i >> 5)) * 32 + (i & 31)];
    if (tid < CH2) { sh[tid][0] = 0.f; sh[tid][33] = 0.f; }
    __syncthreads();

    int oc = tid;
    float wA = w1[oc * 3 + 2], wB = w1[oc * 3 + 1], wC = w1[oc * 3 + 0], bb = b1[oc];
    float sum = 0.f, sq = 0.f;
    for (int r = 0; r < CH2; r++) {
#pragma unroll
        for (int p = 0; p < 32; p++) {
            float y = bb + sh[r][p] * wA + sh[r][p + 1] * wB + sh[r][p + 2] * wC;
            y = fmaxf(y, 0.f);
            sum += y;
            sq += y * y;
        }
    }
    atomicAdd(&g_stats1[oc], (double)sum);
    atomicAdd(&g_stats1[C1 + oc], (double)sq);
}

// ------------------------------------------------------------------
__global__ void k_fin1(const float* __restrict__ gamma, const float* __restrict__ beta) {
    int c = threadIdx.x;
    if (c >= C1) return;
    double N = (double)BSZ * LSP;
    double mean = g_stats1[c] / N;
    double var = g_stats1[C1 + c] / N - mean * mean;
    float a = gamma[c] * (float)(1.0 / sqrt(var + 1e-5));
    g_a1[c] = a;
    g_c1[c] = beta[c] - (float)mean * a;
}

__global__ void k_fin2(const float* __restrict__ gamma, const float* __restrict__ beta) {
    int c = threadIdx.x;
    if (c >= C2) return;
    double N = (double)BSZ * LSP;
    double mean = g_stats2[c] / N;
    double var = g_stats2[C2 + c] / N - mean * mean;
    float a = gamma[c] * (float)(1.0 / sqrt(var + 1e-5));
    g_a2[c] = a;
    g_c2[c] = beta[c] - (float)mean * a;
}

// ------------------------------------------------------------------
// Fused: recompute conv1 -> relu -> BN1 affine -> h1n (smem, zero halos)
//        -> conv2 (packed f32x2) -> +bias -> relu -> store h2 -> stats2.
#define SMEM_FLOATS (4*128*34 + 32*192 + 4*34 + 128*6 + 128)

__global__ void __launch_bounds__(256, 2)
k_conv2(const float* __restrict__ w1, const float* __restrict__ b1,
        const float* __restrict__ w2, const float* __restrict__ b2) {
    extern __shared__ float sm[];
    float* shn  = sm;
    float* sw   = shn + 4 * 128 * 34;
    float* simg = sw + 32 * 192;
    float* sp   = simg + 4 * 34;
    float* red  = sp + 128 * 6;

    int tid = threadIdx.x;
    int bbase = blockIdx.x * 4;

    if (tid < 128) red[tid] = 0.f;
    for (int i = tid; i < 128; i += 256) {
        sp[i * 6 + 0] = w1[i * 3 + 0];
        sp[i * 6 + 1] = w1[i * 3 + 1];
        sp[i * 6 + 2] = w1[i * 3 + 2];
        sp[i * 6 + 3] = b1[i];
        sp[i * 6 + 4] = g_a1[i];
        sp[i * 6 + 5] = g_c1[i];
    }
    for (int i = tid; i < 4 * 32; i += 256) {
        int bl = i >> 5, p = i & 31;
        simg[bl * 34 + p + 1] = g_images[(bbase + bl) * 32 + p];
    }
    if (tid < 4) { simg[tid * 34] = 0.f; simg[tid * 34 + 33] = 0.f; }
    for (int i = tid; i < 4 * 128; i += 256) {
        shn[i * 34 + 0]  = 0.f;
        shn[i * 34 + 33] = 0.f;
    }
    __syncthreads();

    // h1n = a1 * relu(conv1) + c1  (padding positions stay 0)
    for (int idx = tid; idx < 4 * 128 * 32; idx += 256) {
        int bl = idx >> 12, rem = idx & 4095, ic = rem >> 5, p = rem & 31;
        const float* pp = &sp[ic * 6];
        float y = pp[3] + simg[bl * 34 + p] * pp[2] + simg[bl * 34 + p + 1] * pp[1]
                        + simg[bl * 34 + p + 2] * pp[0];
        y = fmaxf(y, 0.f);
        shn[(bl * 128 + ic) * 34 + p + 1] = fmaf(pp[4], y, pp[5]);
    }

    // conv2: thread = (bl, 4 out-channels, 8 positions), positions packed 2-wide
    int bl = tid >> 6;
    int u = tid & 63;
    int ocbase = (u >> 2) * 4;
    int p0 = (u & 3) * 8;

    unsigned long long acc[4][4];
#pragma unroll
    for (int j = 0; j < 4; j++)
#pragma unroll
        for (int i = 0; i < 4; i++) acc[j][i] = 0ull;

    const float* myrow = &shn[bl * 128 * 34];
    for (int chunk = 0; chunk < 4; chunk++) {
        __syncthreads();
        for (int i = tid; i < 32 * 192; i += 256) {
            int icl = i / 192, r = i - icl * 192;
            int k = r >> 6, oc = r & 63;
            sw[i] = w2[((chunk * 32 + icl) * 64 + oc) * 3 + k];
        }
        __syncthreads();
#pragma unroll 2
        for (int icl = 0; icl < 32; icl++) {
            int ic = chunk * 32 + icl;
            const float* xr = myrow + ic * 34 + p0;
            float xv[10];
#pragma unroll
            for (int i = 0; i < 10; i++) xv[i] = xr[i];
            // even pairs (serve tap offsets 0 and 2), odd pairs (tap offset 1)
            unsigned long long xe[5], xo[4];
#pragma unroll
            for (int i = 0; i < 5; i++) xe[i] = pack2(xv[2 * i], xv[2 * i + 1]);
#pragma unroll
            for (int i = 0; i < 4; i++) xo[i] = pack2(xv[2 * i + 1], xv[2 * i + 2]);

            const float* wr = &sw[icl * 192];
#pragma unroll
            for (int j = 0; j < 4; j++) {
                unsigned long long wk2 = dup2(wr[2 * 64 + ocbase + j]);
                unsigned long long wk1 = dup2(wr[1 * 64 + ocbase + j]);
                unsigned long long wk0 = dup2(wr[0 * 64 + ocbase + j]);
#pragma unroll
                for (int i = 0; i < 4; i++) {
                    fma2(acc[j][i], xe[i], wk2);      // xv[2i],   xv[2i+1]
                    fma2(acc[j][i], xo[i], wk1);      // xv[2i+1], xv[2i+2]
                    fma2(acc[j][i], xe[i + 1], wk0);  // xv[2i+2], xv[2i+3]
                }
            }
        }
    }

    int b = bbase + bl;
#pragma unroll
    for (int j = 0; j < 4; j++) {
        int oc = ocbase + j;
        float bb = b2[oc];
        float s = 0.f, sq = 0.f;
#pragma unroll
        for (int i = 0; i < 4; i++) {
            float lo, hi;
            unpack2(acc[j][i], lo, hi);
            float y0 = fmaxf(lo + bb, 0.f);
            float y1 = fmaxf(hi + bb, 0.f);
            g_h2[(b * 64 + oc) * 32 + p0 + 2 * i]     = y0;
            g_h2[(b * 64 + oc) * 32 + p0 + 2 * i + 1] = y1;
            s += y0 + y1;
            sq += y0 * y0 + y1 * y1;
        }
        atomicAdd(&red[oc], s);
        atomicAdd(&red[64 + oc], sq);
    }
    __syncthreads();
    if (tid < 128) atomicAdd(&g_stats2[tid], (double)red[tid]);
}

// ------------------------------------------------------------------
// BN2 affine (padding zeroed AFTER BN) + conv3 + tanh.
__global__ void k_conv3(const float* __restrict__ w3, const float* __restrict__ b3,
                        float* __restrict__ out) {
    __shared__ float sa[64], sc[64], swv[192], sb3;
    int tid = threadIdx.x;
    if (tid < 64) { sa[tid] = g_a2[tid]; sc[tid] = g_c2[tid]; }
    if (tid < 192) swv[tid] = w3[tid];
    if (tid == 0) sb3 = b3[0];
    __syncthreads();

    int t = blockIdx.x * 256 + tid;
    int b = t >> 5, p = t & 31;
    const float* base = &g_h2[b * 64 * 32];
    float acc = sb3;
#pragma unroll 4
    for (int ic = 0; ic < 64; ic++) {
        const float* row = base + ic * 32;
        float a = sa[ic], cs = sc[ic];
        float x0 = fmaf(a, row[p], cs);
        float xm = (p > 0)  ? fmaf(a, row[p - 1], cs) : 0.f;
        float xp = (p < 31) ? fmaf(a, row[p + 1], cs) : 0.f;
        acc += xm * swv[ic * 3 + 2] + x0 * swv[ic * 3 + 1] + xp * swv[ic * 3 + 0];
    }
    out[t] = tanhf(acc);
}

// ------------------------------------------------------------------
extern "C" void kernel_launch(void* const* d_in, const int* in_sizes, int n_in,
                              void* d_out, int out_size) {
    const float* x   = (const float*)d_in[0];
    const float* qp  = (const float*)d_in[1];
    const float* w1  = (const float*)d_in[2];
    const float* b1  = (const float*)d_in[3];
    const float* g1  = (const float*)d_in[4];
    const float* be1 = (const float*)d_in[5];
    const float* w2  = (const float*)d_in[6];
    const float* b2  = (const float*)d_in[7];
    const float* g2  = (const float*)d_in[8];
    const float* be2 = (const float*)d_in[9];
    const float* w3  = (const float*)d_in[10];
    const float* b3  = (const float*)d_in[11];
    float* out = (float*)d_out;

    const int smem_bytes = SMEM_FLOATS * (int)sizeof(float);
    cudaFuncSetAttribute(k_conv2, cudaFuncAttributeMaxDynamicSharedMemorySize, smem_bytes);

    k_zero_stats<<<1, 256>>>();
    k_images<<<(BSZ * 4) / 256, 256>>>(x, qp);
    k_conv1_stats<<<BSZ / CH2, 128>>>(w1, b1);
    k_fin1<<<1, 128>>>(g1, be1);
    k_conv2<<<BSZ / 4, 256, smem_bytes>>>(w1, b1, w2, b2);
    k_fin2<<<1, 64>>>(g2, be2);
    k_conv3<<<(BSZ * 32) / 256, 256>>>(w3, b3, out);
}